// round 6
// baseline (speedup 1.0000x reference)
#include <cuda_runtime.h>
#include <math.h>
#include <stdint.h>

#define BB 256     // batch
#define TT 512     // time steps
#define DIN 128    // input dim
#define HH 256     // hidden
#define G4 1024    // 4*H
#define OUTF 128   // final out features
#define BHH (BB * HH)

// cluster path
#define CLUSTER 8        // CTAs per cluster (one per 32 hidden units)
#define BT 16            // batch rows per cluster
#define JPC 32           // hidden units per CTA
#define WPAD 260
#define HPAD 260
#define W_FLOATS (128 * WPAD)          // 128 gate-rows x 256 k (padded)
#define HBUF_FLOATS (2 * BT * HPAD)    // double-buffered h tile
#define CSMEM_FLOATS (W_FLOATS + HBUF_FLOATS)

// fallback (group-barrier) path
#define NB_CTAS 128
#define NGROUPS 8
#define GROUP_CTAS 16
#define GW_FLOATS (64 * WPAD + 32 * WPAD)

typedef unsigned long long ull;

// ---------------- scratch (device globals; no allocations allowed) ----------
__device__ float g_XP[(size_t)TT * BB * G4];    // x_proj [T,B,4H]
__device__ float g_HSEQ[(size_t)TT * BB * HH];  // layer-0 h sequence [T,B,H]
__device__ float g_HLAST[BHH];                  // final h of a layer
__device__ float g_h[2][BHH];                   // ping-pong h (fallback path)
__device__ unsigned g_count[NGROUPS];           // barrier counters (fallback)

// ---------------- helpers ----------------------------------------------------
__device__ __forceinline__ void ffma2(ull& d, ull a, ull b) {
    asm("fma.rn.f32x2 %0, %1, %2, %0;" : "+l"(d) : "l"(a), "l"(b));
}
__device__ __forceinline__ float red2(ull v) {
    float lo = __uint_as_float((unsigned)(v & 0xffffffffu));
    float hi = __uint_as_float((unsigned)(v >> 32));
    return lo + hi;
}
__device__ __forceinline__ float fsig(float x) {
    return __fdividef(1.f, 1.f + __expf(-x));
}
__device__ __forceinline__ float ftanh(float x) {
    return 2.f * __fdividef(1.f, 1.f + __expf(-2.f * x)) - 1.f;
}
__device__ __forceinline__ uint32_t smem_u32(const void* p) {
    return (uint32_t)__cvta_generic_to_shared(p);
}
__device__ __forceinline__ uint32_t mapa_u32(uint32_t laddr, uint32_t rank) {
    uint32_t r;
    asm("mapa.shared::cluster.u32 %0, %1, %2;" : "=r"(r) : "r"(laddr), "r"(rank));
    return r;
}
__device__ __forceinline__ void st_cluster_f32(uint32_t raddr, float v) {
    asm volatile("st.shared::cluster.f32 [%0], %1;" :: "r"(raddr), "f"(v) : "memory");
}
__device__ __forceinline__ void cluster_sync_() {
    asm volatile("barrier.cluster.arrive.aligned;" ::: "memory");
    asm volatile("barrier.cluster.wait.aligned;" ::: "memory");
}

// ---------------- init (fallback path only) -----------------------------------
__global__ void init_kernel() {
    int i = blockIdx.x * blockDim.x + threadIdx.x;
    if (i < BHH) g_h[0][i] = 0.f;
    if (i < NGROUPS) g_count[i] = 0u;
}

// ---------------- generic GEMM + bias (f32x2) -- validated R3 -----------------
template <int K>
__global__ void gemm_bias_kernel(const float* __restrict__ A,
                                 size_t rowStrideB, size_t strideT,
                                 const float* __restrict__ W,
                                 const float* __restrict__ b1,
                                 const float* __restrict__ b2,
                                 float* __restrict__ outp, int ldOut)
{
    __shared__ __align__(16) float As[64][68];
    __shared__ __align__(16) float Ws[64][68];

    const int t   = blockIdx.z;
    const int bb  = blockIdx.y * 64;
    const int nn  = blockIdx.x * 64;
    const int tid = threadIdx.x;
    const int r0  = tid & 15;
    const int c0  = tid >> 4;

    ull acc2[4][4];
#pragma unroll
    for (int m = 0; m < 4; m++)
#pragma unroll
        for (int n = 0; n < 4; n++) acc2[m][n] = 0ull;

    const float* Abase = A + (size_t)bb * rowStrideB + (size_t)t * strideT;
    const float* Wbase = W + (size_t)nn * K;

    for (int kt = 0; kt < K; kt += 64) {
#pragma unroll
        for (int i = 0; i < 4; i++) {
            int lin = i * 256 + tid;
            int row = lin >> 4;
            int c4  = (lin & 15) * 4;
            *(float4*)&As[row][c4] =
                *(const float4*)(Abase + (size_t)row * rowStrideB + kt + c4);
            *(float4*)&Ws[row][c4] =
                *(const float4*)(Wbase + (size_t)row * K + kt + c4);
        }
        __syncthreads();

#pragma unroll
        for (int k = 0; k < 64; k += 4) {
            ulonglong2 a2[4], w2[4];
#pragma unroll
            for (int m = 0; m < 4; m++) a2[m] = *(ulonglong2*)&As[r0 + 16 * m][k];
#pragma unroll
            for (int n = 0; n < 4; n++) w2[n] = *(ulonglong2*)&Ws[c0 + 16 * n][k];
#pragma unroll
            for (int m = 0; m < 4; m++)
#pragma unroll
                for (int n = 0; n < 4; n++) {
                    ffma2(acc2[m][n], a2[m].x, w2[n].x);
                    ffma2(acc2[m][n], a2[m].y, w2[n].y);
                }
        }
        __syncthreads();
    }

#pragma unroll
    for (int m = 0; m < 4; m++)
#pragma unroll
        for (int n = 0; n < 4; n++) {
            int row = bb + r0 + 16 * m;
            int col = nn + c0 + 16 * n;
            float bias = (b1 != nullptr) ? (b1[col] + b2[col]) : 0.f;
            outp[((size_t)t * BB + row) * ldOut + col] = red2(acc2[m][n]) + bias;
        }
}

// ---------------- cluster-persistent LSTM layer (preferred path) --------------
__global__ void __cluster_dims__(CLUSTER, 1, 1) __launch_bounds__(256, 1)
lstm_cluster_kernel(const float* __restrict__ xp,    // [T,B,4H]
                    const float* __restrict__ Whh,   // [4H,H]
                    float* __restrict__ hseq,        // [T,B,H] or null
                    float* __restrict__ hlast)       // [B,H]
{
    extern __shared__ __align__(16) float sm[];
    float* Ws = sm;                 // [128][WPAD]
    float* Hb = sm + W_FLOATS;      // [2][BT][HPAD]

    const int tid = threadIdx.x;
    uint32_t rank;
    asm("mov.u32 %0, %%cluster_ctarank;" : "=r"(rank));
    const int cid = blockIdx.x / CLUSTER;
    const int bb  = cid * BT;
    const int j0  = (int)rank * JPC;
    const int jl  = tid >> 3;      // 0..31 hidden unit within CTA
    const int br  = tid & 7;       // batch rows br, br+8
    const int j   = j0 + jl;       // global hidden index

    // ---- load W_hh slice: smem row = g*32+jloc <- global row g*HH + j0 + jloc
#pragma unroll
    for (int i = 0; i < 32; i++) {
        int lin  = i * 256 + tid;
        int srow = lin >> 6;
        int c4   = (lin & 63) * 4;
        int g    = srow >> 5;
        int jloc = srow & 31;
        *(float4*)&Ws[srow * WPAD + c4] =
            *(const float4*)(Whh + (size_t)(g * HH + j0 + jloc) * HH + c4);
    }
    for (int i = tid; i < HBUF_FLOATS; i += 256) Hb[i] = 0.f;

    uint32_t hb_loc = smem_u32(Hb);
    uint32_t rbase[CLUSTER];
#pragma unroll
    for (int r = 0; r < CLUSTER; r++) rbase[r] = mapa_u32(hb_loc, (uint32_t)r);

    float cacc[2] = {0.f, 0.f};

    cluster_sync_();   // W + zeroed h visible cluster-wide

    for (int t = 0; t < TT; t++) {
        const float* hp = Hb + (size_t)(t & 1) * BT * HPAD;
        const uint32_t qoff = (uint32_t)(((t + 1) & 1) * BT * HPAD) * 4u;

        float xv[2][4];
        {
            const float* xpt = xp + (size_t)t * BB * G4;
#pragma unroll
            for (int m = 0; m < 2; m++) {
                const float* xr = xpt + (size_t)(bb + br + 8 * m) * G4;
#pragma unroll
                for (int g = 0; g < 4; g++)
                    xv[m][g] = __ldcg(xr + g * HH + j);
            }
        }

        ull acc2[2][4];
#pragma unroll
        for (int m = 0; m < 2; m++)
#pragma unroll
            for (int g = 0; g < 4; g++) acc2[m][g] = 0ull;

#pragma unroll 4
        for (int k = 0; k < HH; k += 4) {
            ulonglong2 h2[2], w2[4];
#pragma unroll
            for (int m = 0; m < 2; m++)
                h2[m] = *(ulonglong2*)&hp[(br + 8 * m) * HPAD + k];
#pragma unroll
            for (int g = 0; g < 4; g++)
                w2[g] = *(ulonglong2*)&Ws[(g * JPC + jl) * WPAD + k];
#pragma unroll
            for (int m = 0; m < 2; m++)
#pragma unroll
                for (int g = 0; g < 4; g++) {
                    ffma2(acc2[m][g], h2[m].x, w2[g].x);
                    ffma2(acc2[m][g], h2[m].y, w2[g].y);
                }
        }

#pragma unroll
        for (int m = 0; m < 2; m++) {
            int b = bb + br + 8 * m;
            float vi = red2(acc2[m][0]) + xv[m][0];
            float vf = red2(acc2[m][1]) + xv[m][1];
            float vg = red2(acc2[m][2]) + xv[m][2];
            float vo = red2(acc2[m][3]) + xv[m][3];

            float ig = fsig(vi);
            float fg = fsig(vf);
            float gg = ftanh(vg);
            float og = fsig(vo);

            float cn = fg * cacc[m] + ig * gg;
            cacc[m] = cn;
            float hn = og * ftanh(cn);

            uint32_t off = qoff + (uint32_t)((br + 8 * m) * HPAD + j) * 4u;
#pragma unroll
            for (int r = 0; r < CLUSTER; r++)
                st_cluster_f32(rbase[r] + off, hn);

            if (hseq != nullptr)
                __stcg(hseq + (size_t)t * BHH + (size_t)b * HH + j, hn);
            if (t == TT - 1)
                hlast[(size_t)b * HH + j] = hn;
        }

        cluster_sync_();   // release stores, acquire peers' h
    }
}

// ---------------- fallback: group-barrier persistent kernel (R3, 10.2ms) ------
__global__ void lstm_group_kernel(const float* __restrict__ xp,
                                  const float* __restrict__ Whh,
                                  float* __restrict__ hbuf,     // [2][B,H]
                                  float* __restrict__ hseq,
                                  float* __restrict__ hlast)
{
    extern __shared__ float smg[];
    float* Ws = smg;              // [64][WPAD]
    float* Hs = smg + 64 * WPAD;  // [32][WPAD]

    const int tid = threadIdx.x;
    const int jt  = blockIdx.x & 15;
    const int bt  = blockIdx.x >> 4;
    const int jj  = jt * 16;
    const int bb  = bt * 32;
    const int jl  = tid >> 3;
    const int br  = tid & 7;
    const int j   = jj + jl;

#pragma unroll
    for (int i = 0; i < 32; i++) {
        int lin  = i * 128 + tid;
        int srow = lin >> 6;
        int c4   = (lin & 63) * 4;
        int g    = srow >> 4;
        int jloc = srow & 15;
        *(float4*)&Ws[srow * WPAD + c4] =
            *(const float4*)(Whh + (size_t)(g * HH + jj + jloc) * HH + c4);
    }

    float cacc[4] = {0.f, 0.f, 0.f, 0.f};
    __syncthreads();

    for (int t = 0; t < TT; t++) {
        const float* hin = hbuf + (size_t)(t & 1) * BHH;
#pragma unroll
        for (int i = 0; i < 16; i++) {
            int lin = i * 128 + tid;
            int row = lin >> 6;
            int c4  = (lin & 63) * 4;
            float4 v = __ldcg((const float4*)(hin + (size_t)(bb + row) * HH + c4));
            *(float4*)&Hs[row * WPAD + c4] = v;
        }
        __syncthreads();

        float xv[4][4];
        {
            const float* xpt = xp + (size_t)t * BB * G4;
#pragma unroll
            for (int m = 0; m < 4; m++) {
                const float* xr = xpt + (size_t)(bb + br + 8 * m) * G4;
#pragma unroll
                for (int g = 0; g < 4; g++)
                    xv[m][g] = __ldg(xr + g * HH + j);
            }
        }

        ull acc2[4][4];
#pragma unroll
        for (int m = 0; m < 4; m++)
#pragma unroll
            for (int g = 0; g < 4; g++) acc2[m][g] = 0ull;

#pragma unroll 4
        for (int k = 0; k < HH; k += 4) {
            ulonglong2 h2[4], w2[4];
#pragma unroll
            for (int m = 0; m < 4; m++)
                h2[m] = *(ulonglong2*)&Hs[(br + 8 * m) * WPAD + k];
#pragma unroll
            for (int g = 0; g < 4; g++)
                w2[g] = *(ulonglong2*)&Ws[(g * 16 + jl) * WPAD + k];
#pragma unroll
            for (int m = 0; m < 4; m++)
#pragma unroll
                for (int g = 0; g < 4; g++) {
                    ffma2(acc2[m][g], h2[m].x, w2[g].x);
                    ffma2(acc2[m][g], h2[m].y, w2[g].y);
                }
        }

        float* hout = hbuf + (size_t)((t + 1) & 1) * BHH;
#pragma unroll
        for (int m = 0; m < 4; m++) {
            int b = bb + br + 8 * m;
            float vi = red2(acc2[m][0]) + xv[m][0];
            float vf = red2(acc2[m][1]) + xv[m][1];
            float vg = red2(acc2[m][2]) + xv[m][2];
            float vo = red2(acc2[m][3]) + xv[m][3];

            float ig = fsig(vi);
            float fg = fsig(vf);
            float gg = ftanh(vg);
            float og = fsig(vo);

            float cn = fg * cacc[m] + ig * gg;
            cacc[m] = cn;
            float hn = og * ftanh(cn);
            __stcg(hout + (size_t)b * HH + j, hn);
            if (hseq != nullptr) hseq[(size_t)t * BHH + (size_t)b * HH + j] = hn;
            if (t == TT - 1) hlast[(size_t)b * HH + j] = hn;
        }

        __syncthreads();
        if (tid == 0) {
            __threadfence();
            atomicAdd(&g_count[bt], 1u);
            unsigned target = (unsigned)(t + 1) * GROUP_CTAS;
            while (*((volatile unsigned*)&g_count[bt]) < target) {}
            __threadfence();
        }
        __syncthreads();
    }
}

// ---------------- launcher ---------------------------------------------------
extern "C" void kernel_launch(void* const* d_in, const int* in_sizes, int n_in,
                              void* d_out, int out_size)
{
    const float* x     = (const float*)d_in[0];
    const float* W_ih0 = (const float*)d_in[1];
    const float* W_hh0 = (const float*)d_in[2];
    const float* b_ih0 = (const float*)d_in[3];
    const float* b_hh0 = (const float*)d_in[4];
    const float* W_ih1 = (const float*)d_in[5];
    const float* W_hh1 = (const float*)d_in[6];
    const float* b_ih1 = (const float*)d_in[7];
    const float* b_hh1 = (const float*)d_in[8];
    const float* W_fc  = (const float*)d_in[9];
    float* outp = (float*)d_out;
    (void)in_sizes; (void)n_in; (void)out_size;

    float *XP, *HSEQ, *HLAST, *Hbuf;
    cudaGetSymbolAddress((void**)&XP,    g_XP);
    cudaGetSymbolAddress((void**)&HSEQ,  g_HSEQ);
    cudaGetSymbolAddress((void**)&HLAST, g_HLAST);
    cudaGetSymbolAddress((void**)&Hbuf,  g_h);

    // deterministic path selection: does this system support cluster launch?
    static int use_cluster = -1;
    if (use_cluster < 0) {
        int dev = 0, v = 0;
        cudaGetDevice(&dev);
        if (cudaDeviceGetAttribute(&v, cudaDevAttrClusterLaunch, dev) != cudaSuccess)
            v = 0;
        use_cluster = v ? 1 : 0;
        cudaFuncSetAttribute(lstm_cluster_kernel,
                             cudaFuncAttributeMaxDynamicSharedMemorySize,
                             CSMEM_FLOATS * (int)sizeof(float));
        cudaFuncSetAttribute(lstm_group_kernel,
                             cudaFuncAttributeMaxDynamicSharedMemorySize,
                             GW_FLOATS * (int)sizeof(float));
        if (use_cluster) {
            int ncl = 0;
            cudaLaunchConfig_t cfg = {};
            cfg.gridDim = dim3(128);
            cfg.blockDim = dim3(256);
            cfg.dynamicSmemBytes = CSMEM_FLOATS * sizeof(float);
            cudaLaunchAttribute at[1];
            at[0].id = cudaLaunchAttributeClusterDimension;
            at[0].val.clusterDim = {CLUSTER, 1, 1};
            cfg.attrs = at; cfg.numAttrs = 1;
            if (cudaOccupancyMaxActiveClusters(&ncl, (void*)lstm_cluster_kernel, &cfg)
                    != cudaSuccess || ncl < 1)
                use_cluster = 0;
        }
    }

    if (use_cluster) {
        const size_t csmemB = CSMEM_FLOATS * sizeof(float);
        gemm_bias_kernel<DIN><<<dim3(16, 4, TT), 256>>>(
            x, (size_t)TT * DIN, (size_t)DIN, W_ih0, b_ih0, b_hh0, XP, G4);
        lstm_cluster_kernel<<<128, 256, csmemB>>>(XP, W_hh0, HSEQ, HLAST);

        gemm_bias_kernel<HH><<<dim3(16, 4, TT), 256>>>(
            HSEQ, (size_t)HH, (size_t)BB * HH, W_ih1, b_ih1, b_hh1, XP, G4);
        lstm_cluster_kernel<<<128, 256, csmemB>>>(XP, W_hh1, nullptr, HLAST);
    } else {
        const size_t gsmemB = GW_FLOATS * sizeof(float);
        init_kernel<<<(BHH + 255) / 256, 256>>>();
        gemm_bias_kernel<DIN><<<dim3(16, 4, TT), 256>>>(
            x, (size_t)TT * DIN, (size_t)DIN, W_ih0, b_ih0, b_hh0, XP, G4);
        lstm_group_kernel<<<NB_CTAS, 128, gsmemB>>>(XP, W_hh0, Hbuf, HSEQ, HLAST);

        init_kernel<<<(BHH + 255) / 256, 256>>>();
        gemm_bias_kernel<HH><<<dim3(16, 4, TT), 256>>>(
            HSEQ, (size_t)HH, (size_t)BB * HH, W_ih1, b_ih1, b_hh1, XP, G4);
        lstm_group_kernel<<<NB_CTAS, 128, gsmemB>>>(XP, W_hh1, Hbuf, nullptr, HLAST);
    }

    // ---------- final FC: out = h_last @ W_fc^T ----------
    gemm_bias_kernel<HH><<<dim3(2, 4, 1), 256>>>(
        HLAST, (size_t)HH, 0, W_fc, nullptr, nullptr, outp, OUTF);
}